// round 12
// baseline (speedup 1.0000x reference)
#include <cuda_runtime.h>

// JointIntegralRegressor: soft-argmax over [16,24,64,64,64] fp32 heatmaps.
// R12: pass1 software-pipelined — double-buffered 8-deep load batches keep
// 8 LDG.128s continuously in flight (no burst/compute bubbles). 85-reg
// budget (minBlocks=3, occ 24 warps/SM). pass2 unchanged (grid=384 warps).

#define DIM_W 64
#define DIM_H 64
#define DIM_D 64
#define SLICES 384                           // 16*24
#define SLICE_ELEMS (DIM_D * DIM_H * DIM_W)  // 262144
#define CHUNKS_PER_SLICE 8
#define CHUNK_ELEMS (SLICE_ELEMS / CHUNKS_PER_SLICE)   // 32768
#define NCHUNKS (SLICES * CHUNKS_PER_SLICE)            // 3072
#define P1_THREADS 256
#define V4_PER_THREAD (CHUNK_ELEMS / 4 / P1_THREADS)   // 32
#define BATCH 8
#define NBATCH (V4_PER_THREAD / BATCH)                 // 4

// Scratch for per-chunk partial moments: (s, sx, sy, sz).
__device__ float4 g_partials[NCHUNKS];

__device__ __forceinline__ void moments(const float4 v, int e,
                                        float& s, float& sx, float& sy, float& sz) {
    const float w0 = (float)(e & (DIM_W - 1));
    const int   hd = e >> 6;
    const float hf = (float)(hd & (DIM_H - 1));
    const float df = (float)(hd >> 6);

    const float e0 = __expf(v.x);
    const float e1 = __expf(v.y);
    const float e2 = __expf(v.z);
    const float e3 = __expf(v.w);

    const float sp = (e0 + e1) + (e2 + e3);
    float inner = fmaf(2.f, e2, e1);
    inner       = fmaf(3.f, e3, inner);

    s  += sp;
    sx += fmaf(w0, sp, inner);
    sy  = fmaf(hf, sp, sy);
    sz  = fmaf(df, sp, sz);
}

__global__ __launch_bounds__(P1_THREADS, 3)   // 85-reg budget: 2x8 float4 buffers
void jir_pass1(const float* __restrict__ in) {
    const int chunk = blockIdx.x;
    const int tid = threadIdx.x;

    const float4* __restrict__ in4 =
        reinterpret_cast<const float4*>(in) + (long long)chunk * (CHUNK_ELEMS / 4);
    const int elem0 = (chunk & (CHUNKS_PER_SLICE - 1)) * CHUNK_ELEMS;

    float s = 0.f, sx = 0.f, sy = 0.f, sz = 0.f;

    float4 va[BATCH], vb[BATCH];

    // Prologue: fill buffer A with batch 0.
    #pragma unroll
    for (int j = 0; j < BATCH; ++j)
        va[j] = __ldcs(&in4[j * P1_THREADS + tid]);

    #pragma unroll
    for (int b = 0; b < NBATCH; ++b) {
        float4* cur = (b & 1) ? vb : va;
        float4* nxt = (b & 1) ? va : vb;

        // Issue next batch's loads first (keeps 8 LDGs in flight during compute).
        if (b + 1 < NBATCH) {
            #pragma unroll
            for (int j = 0; j < BATCH; ++j)
                nxt[j] = __ldcs(&in4[((b + 1) * BATCH + j) * P1_THREADS + tid]);
        }

        // Compute current batch.
        #pragma unroll
        for (int j = 0; j < BATCH; ++j) {
            const int idx4 = (b * BATCH + j) * P1_THREADS + tid;
            moments(cur[j], elem0 + idx4 * 4, s, sx, sy, sz);
        }
    }

    // Block reduction: warp shuffle, then warp-partials through shared memory.
    #pragma unroll
    for (int off = 16; off > 0; off >>= 1) {
        s  += __shfl_down_sync(0xFFFFFFFFu, s,  off);
        sx += __shfl_down_sync(0xFFFFFFFFu, sx, off);
        sy += __shfl_down_sync(0xFFFFFFFFu, sy, off);
        sz += __shfl_down_sync(0xFFFFFFFFu, sz, off);
    }

    __shared__ float4 red[P1_THREADS / 32];
    const int warp = tid >> 5;
    const int lane = tid & 31;
    if (lane == 0) red[warp] = make_float4(s, sx, sy, sz);
    __syncthreads();

    if (tid == 0) {
        float4 acc = red[0];
        #pragma unroll
        for (int i = 1; i < P1_THREADS / 32; ++i) {
            acc.x += red[i].x;
            acc.y += red[i].y;
            acc.z += red[i].z;
            acc.w += red[i].w;
        }
        g_partials[chunk] = acc;
    }
}

// One 32-thread block per slice: lanes 0..7 load one partial each, reduce.
__global__ __launch_bounds__(32)
void jir_pass2(float* __restrict__ out) {
    const int slice = blockIdx.x;
    const int lane = threadIdx.x;

    float s = 0.f, sx = 0.f, sy = 0.f, sz = 0.f;
    if (lane < CHUNKS_PER_SLICE) {
        const float4 p = g_partials[slice * CHUNKS_PER_SLICE + lane];
        s = p.x; sx = p.y; sy = p.z; sz = p.w;
    }

    #pragma unroll
    for (int off = 4; off > 0; off >>= 1) {
        s  += __shfl_down_sync(0xFFFFFFFFu, s,  off);
        sx += __shfl_down_sync(0xFFFFFFFFu, sx, off);
        sy += __shfl_down_sync(0xFFFFFFFFu, sy, off);
        sz += __shfl_down_sync(0xFFFFFFFFu, sz, off);
    }

    if (lane == 0) {
        const float inv = 1.0f / s;
        const float scale = 1.0f / 64.0f;
        out[slice * 3 + 0] = sx * inv * scale - 0.5f;
        out[slice * 3 + 1] = sy * inv * scale - 0.5f;
        out[slice * 3 + 2] = sz * inv * scale - 0.5f;
    }
}

extern "C" void kernel_launch(void* const* d_in, const int* in_sizes, int n_in,
                              void* d_out, int out_size) {
    const float* heatmaps = (const float*)d_in[0];
    float* out = (float*)d_out;

    jir_pass1<<<NCHUNKS, P1_THREADS>>>(heatmaps);
    jir_pass2<<<SLICES, 32>>>(out);
}

// round 13
// speedup vs baseline: 1.0185x; 1.0185x over previous
#include <cuda_runtime.h>

// JointIntegralRegressor: soft-argmax over [16,24,64,64,64] fp32 heatmaps.
// R13: R11's flat 8-deep front-batched loads (proven best codegen: 64-reg
// budget, occ 4, MLP_p1=8) + finer chunks (16/slice) for a smoother last
// wave — safe now because MLP is explicit in BATCH, not tied to chunk size.

#define DIM_W 64
#define DIM_H 64
#define DIM_D 64
#define SLICES 384                           // 16*24
#define SLICE_ELEMS (DIM_D * DIM_H * DIM_W)  // 262144
#define CHUNKS_PER_SLICE 16
#define CHUNK_ELEMS (SLICE_ELEMS / CHUNKS_PER_SLICE)   // 16384
#define NCHUNKS (SLICES * CHUNKS_PER_SLICE)            // 6144
#define P1_THREADS 256
#define V4_PER_THREAD (CHUNK_ELEMS / 4 / P1_THREADS)   // 16
#define BATCH 8
#define NBATCH (V4_PER_THREAD / BATCH)                 // 2

// Scratch for per-chunk partial moments: (s, sx, sy, sz).
__device__ float4 g_partials[NCHUNKS];

__global__ __launch_bounds__(P1_THREADS, 4)   // 64-reg budget (R11 codegen)
void jir_pass1(const float* __restrict__ in) {
    const int chunk = blockIdx.x;
    const int tid = threadIdx.x;

    const float4* __restrict__ in4 =
        reinterpret_cast<const float4*>(in) + (long long)chunk * (CHUNK_ELEMS / 4);
    const int elem0 = (chunk & (CHUNKS_PER_SLICE - 1)) * CHUNK_ELEMS;

    float s = 0.f, sx = 0.f, sy = 0.f, sz = 0.f;

    for (int b = 0; b < NBATCH; ++b) {
        // Front-batched loads: 8 consecutive LDG.128 with no consumer between.
        float4 v[BATCH];
        #pragma unroll
        for (int j = 0; j < BATCH; ++j) {
            v[j] = __ldcs(&in4[(b * BATCH + j) * P1_THREADS + tid]);
        }

        #pragma unroll
        for (int j = 0; j < BATCH; ++j) {
            const int idx4 = (b * BATCH + j) * P1_THREADS + tid;
            const int e  = elem0 + idx4 * 4;
            const float w0 = (float)(e & (DIM_W - 1));
            const int   hd = e >> 6;
            const float hf = (float)(hd & (DIM_H - 1));
            const float df = (float)(hd >> 6);

            const float e0 = __expf(v[j].x);
            const float e1 = __expf(v[j].y);
            const float e2 = __expf(v[j].z);
            const float e3 = __expf(v[j].w);

            const float sp = (e0 + e1) + (e2 + e3);
            // sum_k e_k * (w0 + k) = w0*sp + (e1 + 2*e2 + 3*e3)
            float inner = fmaf(2.f, e2, e1);
            inner       = fmaf(3.f, e3, inner);

            s  += sp;
            sx += fmaf(w0, sp, inner);
            sy  = fmaf(hf, sp, sy);
            sz  = fmaf(df, sp, sz);
        }
    }

    // Block reduction: warp shuffle, then warp-partials through shared memory.
    #pragma unroll
    for (int off = 16; off > 0; off >>= 1) {
        s  += __shfl_down_sync(0xFFFFFFFFu, s,  off);
        sx += __shfl_down_sync(0xFFFFFFFFu, sx, off);
        sy += __shfl_down_sync(0xFFFFFFFFu, sy, off);
        sz += __shfl_down_sync(0xFFFFFFFFu, sz, off);
    }

    __shared__ float4 red[P1_THREADS / 32];
    const int warp = tid >> 5;
    const int lane = tid & 31;
    if (lane == 0) red[warp] = make_float4(s, sx, sy, sz);
    __syncthreads();

    if (tid == 0) {
        float4 acc = red[0];
        #pragma unroll
        for (int i = 1; i < P1_THREADS / 32; ++i) {
            acc.x += red[i].x;
            acc.y += red[i].y;
            acc.z += red[i].z;
            acc.w += red[i].w;
        }
        g_partials[chunk] = acc;
    }
}

// One 32-thread block per slice: lanes 0..15 load one partial each, reduce.
__global__ __launch_bounds__(32)
void jir_pass2(float* __restrict__ out) {
    const int slice = blockIdx.x;
    const int lane = threadIdx.x;

    float s = 0.f, sx = 0.f, sy = 0.f, sz = 0.f;
    if (lane < CHUNKS_PER_SLICE) {
        const float4 p = g_partials[slice * CHUNKS_PER_SLICE + lane];
        s = p.x; sx = p.y; sy = p.z; sz = p.w;
    }

    #pragma unroll
    for (int off = 8; off > 0; off >>= 1) {
        s  += __shfl_down_sync(0xFFFFFFFFu, s,  off);
        sx += __shfl_down_sync(0xFFFFFFFFu, sx, off);
        sy += __shfl_down_sync(0xFFFFFFFFu, sy, off);
        sz += __shfl_down_sync(0xFFFFFFFFu, sz, off);
    }

    if (lane == 0) {
        const float inv = 1.0f / s;
        const float scale = 1.0f / 64.0f;
        out[slice * 3 + 0] = sx * inv * scale - 0.5f;
        out[slice * 3 + 1] = sy * inv * scale - 0.5f;
        out[slice * 3 + 2] = sz * inv * scale - 0.5f;
    }
}

extern "C" void kernel_launch(void* const* d_in, const int* in_sizes, int n_in,
                              void* d_out, int out_size) {
    const float* heatmaps = (const float*)d_in[0];
    float* out = (float*)d_out;

    jir_pass1<<<NCHUNKS, P1_THREADS>>>(heatmaps);
    jir_pass2<<<SLICES, 32>>>(out);
}

// round 14
// speedup vs baseline: 1.0297x; 1.0109x over previous
#include <cuda_runtime.h>

// JointIntegralRegressor: soft-argmax over [16,24,64,64,64] fp32 heatmaps.
// R14: chunk-size gradient continued — 32 chunks/slice (12288 CTAs), each
// thread does exactly ONE 8-deep front-batched load batch (MLP_p1=8, the
// proven R11 codegen: 64-reg budget, occ 4). pass2 reduces 32 partials.

#define DIM_W 64
#define DIM_H 64
#define DIM_D 64
#define SLICES 384                           // 16*24
#define SLICE_ELEMS (DIM_D * DIM_H * DIM_W)  // 262144
#define CHUNKS_PER_SLICE 32
#define CHUNK_ELEMS (SLICE_ELEMS / CHUNKS_PER_SLICE)   // 8192
#define NCHUNKS (SLICES * CHUNKS_PER_SLICE)            // 12288
#define P1_THREADS 256
#define V4_PER_THREAD (CHUNK_ELEMS / 4 / P1_THREADS)   // 8
#define BATCH 8

// Scratch for per-chunk partial moments: (s, sx, sy, sz).
__device__ float4 g_partials[NCHUNKS];

__global__ __launch_bounds__(P1_THREADS, 4)   // 64-reg budget (R11 codegen)
void jir_pass1(const float* __restrict__ in) {
    const int chunk = blockIdx.x;
    const int tid = threadIdx.x;

    const float4* __restrict__ in4 =
        reinterpret_cast<const float4*>(in) + (long long)chunk * (CHUNK_ELEMS / 4);
    const int elem0 = (chunk & (CHUNKS_PER_SLICE - 1)) * CHUNK_ELEMS;

    float s = 0.f, sx = 0.f, sy = 0.f, sz = 0.f;

    // Exactly one front-batched load batch: 8 consecutive LDG.128.
    float4 v[BATCH];
    #pragma unroll
    for (int j = 0; j < BATCH; ++j) {
        v[j] = __ldcs(&in4[j * P1_THREADS + tid]);
    }

    #pragma unroll
    for (int j = 0; j < BATCH; ++j) {
        const int idx4 = j * P1_THREADS + tid;
        const int e  = elem0 + idx4 * 4;
        const float w0 = (float)(e & (DIM_W - 1));
        const int   hd = e >> 6;
        const float hf = (float)(hd & (DIM_H - 1));
        const float df = (float)(hd >> 6);

        const float e0 = __expf(v[j].x);
        const float e1 = __expf(v[j].y);
        const float e2 = __expf(v[j].z);
        const float e3 = __expf(v[j].w);

        const float sp = (e0 + e1) + (e2 + e3);
        // sum_k e_k * (w0 + k) = w0*sp + (e1 + 2*e2 + 3*e3)
        float inner = fmaf(2.f, e2, e1);
        inner       = fmaf(3.f, e3, inner);

        s  += sp;
        sx += fmaf(w0, sp, inner);
        sy  = fmaf(hf, sp, sy);
        sz  = fmaf(df, sp, sz);
    }

    // Block reduction: warp shuffle, then warp-partials through shared memory.
    #pragma unroll
    for (int off = 16; off > 0; off >>= 1) {
        s  += __shfl_down_sync(0xFFFFFFFFu, s,  off);
        sx += __shfl_down_sync(0xFFFFFFFFu, sx, off);
        sy += __shfl_down_sync(0xFFFFFFFFu, sy, off);
        sz += __shfl_down_sync(0xFFFFFFFFu, sz, off);
    }

    __shared__ float4 red[P1_THREADS / 32];
    const int warp = tid >> 5;
    const int lane = tid & 31;
    if (lane == 0) red[warp] = make_float4(s, sx, sy, sz);
    __syncthreads();

    if (tid == 0) {
        float4 acc = red[0];
        #pragma unroll
        for (int i = 1; i < P1_THREADS / 32; ++i) {
            acc.x += red[i].x;
            acc.y += red[i].y;
            acc.z += red[i].z;
            acc.w += red[i].w;
        }
        g_partials[chunk] = acc;
    }
}

// One 32-thread block per slice: all 32 lanes load one partial each, reduce.
__global__ __launch_bounds__(32)
void jir_pass2(float* __restrict__ out) {
    const int slice = blockIdx.x;
    const int lane = threadIdx.x;

    const float4 p = g_partials[slice * CHUNKS_PER_SLICE + lane];
    float s = p.x, sx = p.y, sy = p.z, sz = p.w;

    #pragma unroll
    for (int off = 16; off > 0; off >>= 1) {
        s  += __shfl_down_sync(0xFFFFFFFFu, s,  off);
        sx += __shfl_down_sync(0xFFFFFFFFu, sx, off);
        sy += __shfl_down_sync(0xFFFFFFFFu, sy, off);
        sz += __shfl_down_sync(0xFFFFFFFFu, sz, off);
    }

    if (lane == 0) {
        const float inv = 1.0f / s;
        const float scale = 1.0f / 64.0f;
        out[slice * 3 + 0] = sx * inv * scale - 0.5f;
        out[slice * 3 + 1] = sy * inv * scale - 0.5f;
        out[slice * 3 + 2] = sz * inv * scale - 0.5f;
    }
}

extern "C" void kernel_launch(void* const* d_in, const int* in_sizes, int n_in,
                              void* d_out, int out_size) {
    const float* heatmaps = (const float*)d_in[0];
    float* out = (float*)d_out;

    jir_pass1<<<NCHUNKS, P1_THREADS>>>(heatmaps);
    jir_pass2<<<SLICES, 32>>>(out);
}

// round 15
// speedup vs baseline: 1.0572x; 1.0267x over previous
#include <cuda_runtime.h>

// JointIntegralRegressor: soft-argmax over [16,24,64,64,64] fp32 heatmaps.
// R15: chunk gradient continued — 64 chunks/slice (24576 CTAs) with
// 128-thread blocks so each thread still does exactly ONE 8-deep
// front-batched load batch (MLP_p1=8, 64-reg budget preserved).

#define DIM_W 64
#define DIM_H 64
#define DIM_D 64
#define SLICES 384                           // 16*24
#define SLICE_ELEMS (DIM_D * DIM_H * DIM_W)  // 262144
#define CHUNKS_PER_SLICE 64
#define CHUNK_ELEMS (SLICE_ELEMS / CHUNKS_PER_SLICE)   // 4096
#define NCHUNKS (SLICES * CHUNKS_PER_SLICE)            // 24576
#define P1_THREADS 128
#define V4_PER_THREAD (CHUNK_ELEMS / 4 / P1_THREADS)   // 8
#define BATCH 8

// Scratch for per-chunk partial moments: (s, sx, sy, sz).
__device__ float4 g_partials[NCHUNKS];

__global__ __launch_bounds__(P1_THREADS, 8)   // 64-reg budget, 32 warps/SM
void jir_pass1(const float* __restrict__ in) {
    const int chunk = blockIdx.x;
    const int tid = threadIdx.x;

    const float4* __restrict__ in4 =
        reinterpret_cast<const float4*>(in) + (long long)chunk * (CHUNK_ELEMS / 4);
    const int elem0 = (chunk & (CHUNKS_PER_SLICE - 1)) * CHUNK_ELEMS;

    float s = 0.f, sx = 0.f, sy = 0.f, sz = 0.f;

    // Exactly one front-batched load batch: 8 consecutive LDG.128.
    float4 v[BATCH];
    #pragma unroll
    for (int j = 0; j < BATCH; ++j) {
        v[j] = __ldcs(&in4[j * P1_THREADS + tid]);
    }

    #pragma unroll
    for (int j = 0; j < BATCH; ++j) {
        const int idx4 = j * P1_THREADS + tid;
        const int e  = elem0 + idx4 * 4;
        const float w0 = (float)(e & (DIM_W - 1));
        const int   hd = e >> 6;
        const float hf = (float)(hd & (DIM_H - 1));
        const float df = (float)(hd >> 6);

        const float e0 = __expf(v[j].x);
        const float e1 = __expf(v[j].y);
        const float e2 = __expf(v[j].z);
        const float e3 = __expf(v[j].w);

        const float sp = (e0 + e1) + (e2 + e3);
        // sum_k e_k * (w0 + k) = w0*sp + (e1 + 2*e2 + 3*e3)
        float inner = fmaf(2.f, e2, e1);
        inner       = fmaf(3.f, e3, inner);

        s  += sp;
        sx += fmaf(w0, sp, inner);
        sy  = fmaf(hf, sp, sy);
        sz  = fmaf(df, sp, sz);
    }

    // Block reduction: warp shuffle, then 4 warp-partials via shared memory.
    #pragma unroll
    for (int off = 16; off > 0; off >>= 1) {
        s  += __shfl_down_sync(0xFFFFFFFFu, s,  off);
        sx += __shfl_down_sync(0xFFFFFFFFu, sx, off);
        sy += __shfl_down_sync(0xFFFFFFFFu, sy, off);
        sz += __shfl_down_sync(0xFFFFFFFFu, sz, off);
    }

    __shared__ float4 red[P1_THREADS / 32];
    const int warp = tid >> 5;
    const int lane = tid & 31;
    if (lane == 0) red[warp] = make_float4(s, sx, sy, sz);
    __syncthreads();

    if (tid == 0) {
        float4 acc = red[0];
        #pragma unroll
        for (int i = 1; i < P1_THREADS / 32; ++i) {
            acc.x += red[i].x;
            acc.y += red[i].y;
            acc.z += red[i].z;
            acc.w += red[i].w;
        }
        g_partials[chunk] = acc;
    }
}

// One 64-thread block per slice: 64 lanes load one partial each, reduce via
// shared memory + warp shuffle (fixed order -> deterministic).
__global__ __launch_bounds__(64)
void jir_pass2(float* __restrict__ out) {
    const int slice = blockIdx.x;
    const int tid = threadIdx.x;

    const float4 p = g_partials[slice * CHUNKS_PER_SLICE + tid];
    float s = p.x, sx = p.y, sy = p.z, sz = p.w;

    #pragma unroll
    for (int off = 16; off > 0; off >>= 1) {
        s  += __shfl_down_sync(0xFFFFFFFFu, s,  off);
        sx += __shfl_down_sync(0xFFFFFFFFu, sx, off);
        sy += __shfl_down_sync(0xFFFFFFFFu, sy, off);
        sz += __shfl_down_sync(0xFFFFFFFFu, sz, off);
    }

    __shared__ float4 red[2];
    if ((tid & 31) == 0) red[tid >> 5] = make_float4(s, sx, sy, sz);
    __syncthreads();

    if (tid == 0) {
        const float fs  = red[0].x + red[1].x;
        const float fsx = red[0].y + red[1].y;
        const float fsy = red[0].z + red[1].z;
        const float fsz = red[0].w + red[1].w;
        const float inv = 1.0f / fs;
        const float scale = 1.0f / 64.0f;
        out[slice * 3 + 0] = fsx * inv * scale - 0.5f;
        out[slice * 3 + 1] = fsy * inv * scale - 0.5f;
        out[slice * 3 + 2] = fsz * inv * scale - 0.5f;
    }
}

extern "C" void kernel_launch(void* const* d_in, const int* in_sizes, int n_in,
                              void* d_out, int out_size) {
    const float* heatmaps = (const float*)d_in[0];
    float* out = (float*)d_out;

    jir_pass1<<<NCHUNKS, P1_THREADS>>>(heatmaps);
    jir_pass2<<<SLICES, 64>>>(out);
}